// round 4
// baseline (speedup 1.0000x reference)
#include <cuda_runtime.h>
#include <cuda_bf16.h>
#include <cstdint>

// Problem constants
#define NKV    8
#define GRP    4
#define NH     32
#define BQ     16
#define HD     128
#define CACHE  32736
#define KVLEN  32752            // CACHE + BQ; positions >= KVLEN are fully masked (underflow)
#define ROWS   64               // GRP * BQ query rows per kv head
#define NCHUNK 64
#define CHUNK  512              // positions per CTA (4 tiles of 128)
#define TPOS   128              // tile positions
#define NTILE  (CHUNK / TPOS)
#define NEGINF (-1e30f)

#define SMEM_FLOATS (ROWS*HD + HD*TPOS + TPOS*HD + ROWS*TPOS)   // 49152
#define SMEM_BYTES  (SMEM_FLOATS * 4)                            // 196608

// Split-KV scratch (no cudaMalloc allowed -> __device__ globals)
__device__ float g_acc[(size_t)NKV * NCHUNK * ROWS * HD];   // 16 MB
__device__ float g_m[NKV * NCHUNK * ROWS];
__device__ float g_l[NKV * NCHUNK * ROWS];

// ---------------------------------------------------------------------------
// Kernel 1: per-(chunk, kv-head) partial flash attention.
// Block: 256 threads (8 warps). Warp w owns query rows [w*8, w*8+8).
// Lane owns positions {lane, lane+32, lane+64, lane+96} within a 128-pos tile.
// ---------------------------------------------------------------------------
__global__ __launch_bounds__(256, 1)
void attn_partial(const float* __restrict__ q,
                  const float* __restrict__ keys,
                  const float* __restrict__ kT_cache,
                  const float* __restrict__ values,
                  const float* __restrict__ v_cache,
                  const float* __restrict__ kq_scale)
{
    extern __shared__ float smem[];
    float* q_sh  = smem;                       // [ROWS][HD]
    float* kT_sh = q_sh  + ROWS * HD;          // [HD][TPOS]  (K transposed)
    float* v_sh  = kT_sh + HD * TPOS;          // [TPOS][HD]
    float* p_sh  = v_sh  + TPOS * HD;          // [ROWS][TPOS]

    const int chunk = blockIdx.x;
    const int k     = blockIdx.y;
    const int tid   = threadIdx.x;
    const int lane  = tid & 31;
    const int w     = tid >> 5;

    const float scale = kq_scale[0];

    // ---- load Q for this kv head: contiguous 64x128 block ----
    {
        const float4* qg = (const float4*)(q + (size_t)k * ROWS * HD);
        float4* q4 = (float4*)q_sh;
        #pragma unroll
        for (int i = 0; i < 8; i++) q4[tid + i * 256] = qg[tid + i * 256];
    }

    float acc[8][4];
    float m[8], l[8];
    #pragma unroll
    for (int r = 0; r < 8; r++) {
        m[r] = NEGINF; l[r] = 0.f;
        #pragma unroll
        for (int j = 0; j < 4; j++) acc[r][j] = 0.f;
    }

    const int p_base = chunk * CHUNK;
    const float* qrow = q_sh + w * 8 * HD;

    for (int tile = 0; tile < NTILE; tile++) {
        const int p0 = p_base + tile * TPOS;
        __syncthreads();   // protect smem reuse across tiles (also orders Q load)

        // ---- load K^T tile [HD][TPOS] and V tile [TPOS][HD] ----
        if (p0 + TPOS <= CACHE) {
            // fast vectorized path: pure cache tile
            const float* kg = kT_cache + (size_t)k * HD * CACHE;
            const float* vg = v_cache  + (size_t)k * CACHE * HD;
            #pragma unroll
            for (int i = 0; i < 16; i++) {
                int idx = tid + i * 256;           // 0..4095
                int d = idx >> 5, tq = idx & 31;
                ((float4*)kT_sh)[d * 32 + tq] =
                    ((const float4*)(kg + (size_t)d * CACHE + p0))[tq];
            }
            #pragma unroll
            for (int i = 0; i < 16; i++) {
                int idx = tid + i * 256;
                int t = idx >> 5, dq = idx & 31;
                ((float4*)v_sh)[t * 32 + dq] =
                    ((const float4*)(vg + (size_t)(p0 + t) * HD))[dq];
            }
        } else {
            // mixed / tail tile: scalar path (only last tile of last chunk)
            for (int i = 0; i < 64; i++) {
                int idx = tid + i * 256;           // 0..16383
                int d = idx >> 7, t = idx & 127;
                int p = p0 + t;
                float kv = 0.f;
                if (p < CACHE)
                    kv = kT_cache[(size_t)k * HD * CACHE + (size_t)d * CACHE + p];
                else if (p < KVLEN)
                    kv = keys[((size_t)k * BQ + (p - CACHE)) * HD + d] * scale;
                kT_sh[d * TPOS + t] = kv;
            }
            for (int i = 0; i < 64; i++) {
                int idx = tid + i * 256;
                int t = idx >> 7, d = idx & 127;
                int p = p0 + t;
                float vv = 0.f;
                if (p < CACHE)
                    vv = v_cache[(size_t)k * CACHE * HD + (size_t)p * HD + d];
                else if (p < KVLEN)
                    vv = fmaxf(values[((size_t)k * BQ + (p - CACHE)) * HD + d], -10000.f);
                v_sh[t * HD + d] = vv;
            }
        }
        __syncthreads();

        // ---- QK: s[8 rows][4 pos] per lane ----
        float s[8][4];
        #pragma unroll
        for (int r = 0; r < 8; r++)
            #pragma unroll
            for (int j = 0; j < 4; j++) s[r][j] = 0.f;

        #pragma unroll 4
        for (int d = 0; d < HD; d++) {
            float k0 = kT_sh[d * TPOS + lane];
            float k1 = kT_sh[d * TPOS + lane + 32];
            float k2 = kT_sh[d * TPOS + lane + 64];
            float k3 = kT_sh[d * TPOS + lane + 96];
            #pragma unroll
            for (int r = 0; r < 8; r++) {
                float qv = qrow[r * HD + d];
                s[r][0] = fmaf(qv, k0, s[r][0]);
                s[r][1] = fmaf(qv, k1, s[r][1]);
                s[r][2] = fmaf(qv, k2, s[r][2]);
                s[r][3] = fmaf(qv, k3, s[r][3]);
            }
        }

        // ---- mask tail (positions >= KVLEN) ----
        if (p0 + TPOS > KVLEN) {
            #pragma unroll
            for (int j = 0; j < 4; j++) {
                if (p0 + lane + 32 * j >= KVLEN) {
                    #pragma unroll
                    for (int r = 0; r < 8; r++) s[r][j] = NEGINF;
                }
            }
        }

        // ---- online softmax update + stage P to shared ----
        #pragma unroll
        for (int r = 0; r < 8; r++) {
            float mx = fmaxf(fmaxf(s[r][0], s[r][1]), fmaxf(s[r][2], s[r][3]));
            #pragma unroll
            for (int o = 16; o >= 1; o >>= 1)
                mx = fmaxf(mx, __shfl_xor_sync(0xffffffffu, mx, o));
            float mn   = fmaxf(m[r], mx);
            float corr = __expf(m[r] - mn);
            float psum = 0.f;
            #pragma unroll
            for (int j = 0; j < 4; j++) {
                float pv = __expf(s[r][j] - mn);
                s[r][j] = pv;
                psum += pv;
            }
            #pragma unroll
            for (int o = 16; o >= 1; o >>= 1)
                psum += __shfl_xor_sync(0xffffffffu, psum, o);
            l[r] = l[r] * corr + psum;
            m[r] = mn;
            #pragma unroll
            for (int j = 0; j < 4; j++) acc[r][j] *= corr;

            float* prow = p_sh + (w * 8 + r) * TPOS;
            prow[lane]      = s[r][0];
            prow[lane + 32] = s[r][1];
            prow[lane + 64] = s[r][2];
            prow[lane + 96] = s[r][3];
        }
        __syncwarp();   // P rows are private to this warp

        // ---- PV: acc[8 rows][4 cols] per lane; lane owns cols {lane+32c} ----
        #pragma unroll 2
        for (int t = 0; t < TPOS; t++) {
            float v0 = v_sh[t * HD + lane];
            float v1 = v_sh[t * HD + lane + 32];
            float v2 = v_sh[t * HD + lane + 64];
            float v3 = v_sh[t * HD + lane + 96];
            #pragma unroll
            for (int r = 0; r < 8; r++) {
                float pv = p_sh[(w * 8 + r) * TPOS + t];
                acc[r][0] = fmaf(pv, v0, acc[r][0]);
                acc[r][1] = fmaf(pv, v1, acc[r][1]);
                acc[r][2] = fmaf(pv, v2, acc[r][2]);
                acc[r][3] = fmaf(pv, v3, acc[r][3]);
            }
        }
    }

    // ---- write partials ----
    const size_t base = ((size_t)k * NCHUNK + chunk) * ROWS;
    #pragma unroll
    for (int r = 0; r < 8; r++) {
        int row = w * 8 + r;
        size_t ab = (base + row) * HD;
        g_acc[ab + lane]      = acc[r][0];
        g_acc[ab + lane + 32] = acc[r][1];
        g_acc[ab + lane + 64] = acc[r][2];
        g_acc[ab + lane + 96] = acc[r][3];
        if (lane == 0) {
            g_m[base + row] = m[r];
            g_l[base + row] = l[r];
        }
    }
}

// ---------------------------------------------------------------------------
// Kernel 2: merge split-KV partials -> head_outs
// grid (ROWS, NKV), 128 threads (one per head dim)
// ---------------------------------------------------------------------------
__global__ void attn_reduce(float* __restrict__ out)
{
    const int row = blockIdx.x;
    const int k   = blockIdx.y;
    const int d   = threadIdx.x;

    __shared__ float sm[NCHUNK], sl[NCHUNK];
    if (d < NCHUNK) {
        sm[d] = g_m[(k * NCHUNK + d) * ROWS + row];
        sl[d] = g_l[(k * NCHUNK + d) * ROWS + row];
    }
    __syncthreads();

    float M = NEGINF;
    #pragma unroll 8
    for (int c = 0; c < NCHUNK; c++) M = fmaxf(M, sm[c]);

    float L = 0.f, o = 0.f;
    for (int c = 0; c < NCHUNK; c++) {
        float wgt = __expf(sm[c] - M);
        L += sl[c] * wgt;
        o += wgt * g_acc[(((size_t)k * NCHUNK + c) * ROWS + row) * HD + d];
    }
    o /= L;

    const int g = row >> 4, b = row & 15;
    out[(((size_t)(k * GRP + g) * BQ) + b) * HD + d] = o;
}

// ---------------------------------------------------------------------------
// Kernel 3: scaled_keys / scaled_values outputs
// ---------------------------------------------------------------------------
__global__ void prep_kv(const float* __restrict__ keys,
                        const float* __restrict__ values,
                        const float* __restrict__ kq_scale,
                        float* __restrict__ out_sk,
                        float* __restrict__ out_sv)
{
    int i = blockIdx.x * blockDim.x + threadIdx.x;
    if (i < NKV * BQ * HD) {
        out_sk[i] = keys[i] * kq_scale[0];
        out_sv[i] = fmaxf(values[i], -10000.f);
    }
}

extern "C" void kernel_launch(void* const* d_in, const int* in_sizes, int n_in,
                              void* d_out, int out_size)
{
    const float* q     = (const float*)d_in[0];
    const float* keys  = (const float*)d_in[1];
    const float* ktc   = (const float*)d_in[2];
    const float* vals  = (const float*)d_in[3];
    const float* vc    = (const float*)d_in[4];
    // d_in[5] = attn_bias: only masks the pad tail, which underflows -> unused
    const float* scale = (const float*)d_in[6];
    float* out = (float*)d_out;

    cudaFuncSetAttribute(attn_partial,
                         cudaFuncAttributeMaxDynamicSharedMemorySize, SMEM_BYTES);

    dim3 g1(NCHUNK, NKV);
    attn_partial<<<g1, 256, SMEM_BYTES>>>(q, keys, ktc, vals, vc, scale);
    attn_reduce<<<dim3(ROWS, NKV), HD>>>(out);

    const int HEAD_OUT = NH * BQ * HD;        // 65536
    const int KV_OUT   = NKV * BQ * HD;       // 16384
    if (out_size >= HEAD_OUT + 2 * KV_OUT) {
        prep_kv<<<64, 256>>>(keys, vals, scale,
                             out + HEAD_OUT, out + HEAD_OUT + KV_OUT);
    }
}

// round 5
// speedup vs baseline: 2.0190x; 2.0190x over previous
#include <cuda_runtime.h>
#include <cuda_bf16.h>
#include <cstdint>

// ---------------- problem constants ----------------
#define NKV    8
#define GRP    4
#define NH     32
#define BQ     16
#define HD     128
#define CACHE  32736
#define KVLEN  32752              // CACHE + BQ; pos >= KVLEN fully masked
#define ROWS   64                 // GRP*BQ query rows per kv head
#define TPOS   128                // positions per tile
#define NTILES 256                // 256*128 = 32768 >= KVLEN (tile 255 partial)
#define NCHUNK 37                 // 37*8 = 296 CTAs = 2 exact waves on 148 SMs
#define TILES_PER_CHUNK 7         // 37*7 = 259 >= 256
#define NPART  (NKV*NCHUNK*2)     // 592 partials (2 pos-halves per chunk)
#define NEGINF (-1e30f)

// smem layout (bf16 element offsets), all tiles padded pitch 136 (16B-aligned rows,
// 17-stride in 16B units -> conflict-free LDSM and STS)
#define QP 136
#define KP 136
#define VP 136
#define OFF_QHI 0
#define OFF_QLO (ROWS*QP)                  // 8704
#define OFF_KHI (2*ROWS*QP)                // 17408
#define OFF_KLO (OFF_KHI + HD*KP)          // 34816
#define OFF_VHI (OFF_KLO + HD*KP)          // 52224
#define OFF_VLO (OFF_VHI + TPOS*VP)        // 69632
#define SMEM_ELEMS (OFF_VLO + TPOS*VP)     // 87040
#define SMEM_BYTES (SMEM_ELEMS*2)          // 174080

// split-KV scratch (no cudaMalloc -> __device__ globals)
__device__ float g_acc[(size_t)NPART * ROWS * HD];   // ~19.4 MB
__device__ float g_m[NPART * ROWS];
__device__ float g_l[NPART * ROWS];

// ---------------- PTX helpers ----------------
__device__ __forceinline__ void ldsm4(uint32_t r[4], uint32_t a) {
    asm volatile("ldmatrix.sync.aligned.m8n8.x4.shared.b16 {%0,%1,%2,%3},[%4];"
                 : "=r"(r[0]), "=r"(r[1]), "=r"(r[2]), "=r"(r[3]) : "r"(a));
}
__device__ __forceinline__ void ldsm4t(uint32_t r[4], uint32_t a) {
    asm volatile("ldmatrix.sync.aligned.m8n8.x4.trans.shared.b16 {%0,%1,%2,%3},[%4];"
                 : "=r"(r[0]), "=r"(r[1]), "=r"(r[2]), "=r"(r[3]) : "r"(a));
}
__device__ __forceinline__ void mma16816(float& c0, float& c1, float& c2, float& c3,
                                         uint32_t a0, uint32_t a1, uint32_t a2, uint32_t a3,
                                         uint32_t b0, uint32_t b1) {
    asm volatile("mma.sync.aligned.m16n8k16.row.col.f32.bf16.bf16.f32 "
                 "{%0,%1,%2,%3},{%4,%5,%6,%7},{%8,%9},{%0,%1,%2,%3};"
                 : "+f"(c0), "+f"(c1), "+f"(c2), "+f"(c3)
                 : "r"(a0), "r"(a1), "r"(a2), "r"(a3), "r"(b0), "r"(b1));
}
__device__ __forceinline__ uint32_t pk(__nv_bfloat16 a, __nv_bfloat16 b) {
    return (uint32_t)__bfloat16_as_ushort(a) | ((uint32_t)__bfloat16_as_ushort(b) << 16);
}
// split f into bf16 hi + bf16 lo (residual)
__device__ __forceinline__ void cvt_hl(float f, __nv_bfloat16& h, __nv_bfloat16& l) {
    h = __float2bfloat16_rn(f);
    l = __float2bfloat16_rn(f - __bfloat162float(h));
}
__device__ __forceinline__ void store_hl4(__nv_bfloat16* hp, __nv_bfloat16* lp, float4 v) {
    __nv_bfloat16 h0, h1, h2, h3, l0, l1, l2, l3;
    cvt_hl(v.x, h0, l0); cvt_hl(v.y, h1, l1);
    cvt_hl(v.z, h2, l2); cvt_hl(v.w, h3, l3);
    uint2 hh = make_uint2(pk(h0, h1), pk(h2, h3));
    uint2 ll = make_uint2(pk(l0, l1), pk(l2, l3));
    *(uint2*)hp = hh;
    *(uint2*)lp = ll;
}

// ---------------------------------------------------------------------------
// Kernel 1: tensor-core partial flash attention.
// grid (NCHUNK, NKV), 256 threads (8 warps).
// warp w: mtile = w&3 (rows mtile*16..+16), phalf = w>>2 (pos half of tile).
// Each (warp, phalf) keeps an independent online-softmax state -> merged in reduce.
// ---------------------------------------------------------------------------
__global__ void __launch_bounds__(256, 1)
attn_mma(const float* __restrict__ q,
         const float* __restrict__ keys,
         const float* __restrict__ kT,
         const float* __restrict__ values,
         const float* __restrict__ vc,
         const float* __restrict__ kq_scale)
{
    extern __shared__ __nv_bfloat16 sm[];
    const int chunk = blockIdx.x;
    const int k     = blockIdx.y;
    const int tid   = threadIdx.x;
    const int lane  = tid & 31;
    const int w     = tid >> 5;
    const int mtile = w & 3;
    const int phalf = w >> 2;
    const float scale = kq_scale[0];

    // ---- Q load + hi/lo convert (once) ----
    {
        const float4* qg = (const float4*)(q + (size_t)k * ROWS * HD);
        #pragma unroll
        for (int i = 0; i < 8; i++) {
            int idx = tid + i * 256;         // 0..2047
            int r = idx >> 5, f = (idx & 31) * 4;
            store_hl4(sm + OFF_QHI + r * QP + f, sm + OFF_QLO + r * QP + f, qg[idx]);
        }
    }

    const uint32_t smem_b = (uint32_t)__cvta_generic_to_shared(sm);
    const int lrow = lane & 15;
    const int lcol = (lane >> 4) * 8;

    // per-lane ldmatrix bases (bytes)
    const uint32_t qhi_b = smem_b + (uint32_t)(OFF_QHI + (mtile * 16 + lrow) * QP + lcol) * 2;
    const uint32_t qlo_b = smem_b + (uint32_t)(OFF_QLO + (mtile * 16 + lrow) * QP + lcol) * 2;
    const uint32_t khi_b = smem_b + (uint32_t)(OFF_KHI + lrow * KP + phalf * 64 + lcol) * 2;
    const uint32_t klo_b = smem_b + (uint32_t)(OFF_KLO + lrow * KP + phalf * 64 + lcol) * 2;
    const uint32_t vhi_b = smem_b + (uint32_t)(OFF_VHI + (phalf * 64 + lrow) * VP + lcol) * 2;
    const uint32_t vlo_b = smem_b + (uint32_t)(OFF_VLO + (phalf * 64 + lrow) * VP + lcol) * 2;

    float o[16][4];
    #pragma unroll
    for (int n = 0; n < 16; n++)
        #pragma unroll
        for (int j = 0; j < 4; j++) o[n][j] = 0.f;
    float stmA = NEGINF, stmB = NEGINF, stlA = 0.f, stlB = 0.f;

    const int t0 = chunk * TILES_PER_CHUNK;
    const int t1 = (t0 + TILES_PER_CHUNK < NTILES) ? t0 + TILES_PER_CHUNK : NTILES;

    for (int t = t0; t < t1; t++) {
        const int pos0 = t * TPOS;
        __syncthreads();                       // previous tile compute done

        // ---- load + convert K^T [d][pos] and V [pos][d] tiles ----
        if (pos0 + TPOS <= CACHE) {
            #pragma unroll
            for (int i = 0; i < 16; i++) {
                int idx = tid + i * 256;       // 0..4095
                int d = idx >> 5, f = (idx & 31) * 4;
                float4 v4 = *(const float4*)(kT + ((size_t)k * HD + d) * CACHE + pos0 + f);
                store_hl4(sm + OFF_KHI + d * KP + f, sm + OFF_KLO + d * KP + f, v4);
            }
            #pragma unroll
            for (int i = 0; i < 16; i++) {
                int idx = tid + i * 256;
                int p = idx >> 5, f = (idx & 31) * 4;
                float4 v4 = *(const float4*)(vc + ((size_t)k * CACHE + pos0 + p) * HD + f);
                store_hl4(sm + OFF_VHI + p * VP + f, sm + OFF_VLO + p * VP + f, v4);
            }
        } else {
            // tail tile (only tile 255): mix of cache / new / pad
            for (int i = 0; i < 64; i++) {
                int idx = tid + i * 256;       // 0..16383
                int d = idx >> 7, p = idx & 127;
                int gp = pos0 + p;
                float f = 0.f;
                if (gp < CACHE)      f = kT[((size_t)k * HD + d) * CACHE + gp];
                else if (gp < KVLEN) f = keys[(k * BQ + (gp - CACHE)) * HD + d] * scale;
                __nv_bfloat16 h, l; cvt_hl(f, h, l);
                sm[OFF_KHI + d * KP + p] = h;
                sm[OFF_KLO + d * KP + p] = l;
            }
            for (int i = 0; i < 64; i++) {
                int idx = tid + i * 256;
                int p = idx >> 7, d = idx & 127;
                int gp = pos0 + p;
                float f = 0.f;
                if (gp < CACHE)      f = vc[((size_t)k * CACHE + gp) * HD + d];
                else if (gp < KVLEN) f = fmaxf(values[(k * BQ + (gp - CACHE)) * HD + d], -10000.f);
                __nv_bfloat16 h, l; cvt_hl(f, h, l);
                sm[OFF_VHI + p * VP + d] = h;
                sm[OFF_VLO + p * VP + d] = l;
            }
        }
        __syncthreads();

        // ---- QK: S[m16][64 pos] = Q·K^T, 3 bf16 split terms ----
        float s[8][4];
        #pragma unroll
        for (int n = 0; n < 8; n++)
            #pragma unroll
            for (int j = 0; j < 4; j++) s[n][j] = 0.f;

        #pragma unroll 1
        for (int term = 0; term < 3; term++) {
            uint32_t qb = (term == 1) ? qlo_b : qhi_b;   // (hi,hi),(lo,hi),(hi,lo)
            uint32_t kb = (term == 2) ? klo_b : khi_b;
            #pragma unroll
            for (int ks = 0; ks < 8; ks++) {
                uint32_t a[4];
                ldsm4(a, qb + ks * 32);                  // 16 elems * 2B
                #pragma unroll
                for (int nb = 0; nb < 4; nb++) {
                    uint32_t b[4];
                    ldsm4t(b, kb + (uint32_t)(ks * 16 * KP + nb * 16) * 2);
                    mma16816(s[2*nb][0], s[2*nb][1], s[2*nb][2], s[2*nb][3],
                             a[0], a[1], a[2], a[3], b[0], b[1]);
                    mma16816(s[2*nb+1][0], s[2*nb+1][1], s[2*nb+1][2], s[2*nb+1][3],
                             a[0], a[1], a[2], a[3], b[2], b[3]);
                }
            }
        }

        // ---- mask pad positions (tile 255 only) ----
        if (pos0 + TPOS > KVLEN) {
            int cbase = pos0 + phalf * 64 + 2 * (lane & 3);
            #pragma unroll
            for (int n = 0; n < 8; n++) {
                if (cbase + n * 8     >= KVLEN) { s[n][0] = NEGINF; s[n][2] = NEGINF; }
                if (cbase + n * 8 + 1 >= KVLEN) { s[n][1] = NEGINF; s[n][3] = NEGINF; }
            }
        }

        // ---- online softmax (rows rA = lane>>2, rB = rA+8 of this mtile) ----
        float mxA = NEGINF, mxB = NEGINF;
        #pragma unroll
        for (int n = 0; n < 8; n++) {
            mxA = fmaxf(mxA, fmaxf(s[n][0], s[n][1]));
            mxB = fmaxf(mxB, fmaxf(s[n][2], s[n][3]));
        }
        mxA = fmaxf(mxA, __shfl_xor_sync(0xffffffffu, mxA, 1));
        mxA = fmaxf(mxA, __shfl_xor_sync(0xffffffffu, mxA, 2));
        mxB = fmaxf(mxB, __shfl_xor_sync(0xffffffffu, mxB, 1));
        mxB = fmaxf(mxB, __shfl_xor_sync(0xffffffffu, mxB, 2));
        float mnA = fmaxf(stmA, mxA), mnB = fmaxf(stmB, mxB);
        float cA = __expf(stmA - mnA), cB = __expf(stmB - mnB);

        uint32_t ph[8][2], pl[8][2];
        float sumA = 0.f, sumB = 0.f;
        #pragma unroll
        for (int n = 0; n < 8; n++) {
            float p0 = __expf(s[n][0] - mnA), p1 = __expf(s[n][1] - mnA);
            float p2 = __expf(s[n][2] - mnB), p3 = __expf(s[n][3] - mnB);
            sumA += p0 + p1; sumB += p2 + p3;
            __nv_bfloat16 h0, h1, h2, h3, l0, l1, l2, l3;
            cvt_hl(p0, h0, l0); cvt_hl(p1, h1, l1);
            cvt_hl(p2, h2, l2); cvt_hl(p3, h3, l3);
            ph[n][0] = pk(h0, h1); ph[n][1] = pk(h2, h3);
            pl[n][0] = pk(l0, l1); pl[n][1] = pk(l2, l3);
        }
        sumA += __shfl_xor_sync(0xffffffffu, sumA, 1);
        sumA += __shfl_xor_sync(0xffffffffu, sumA, 2);
        sumB += __shfl_xor_sync(0xffffffffu, sumB, 1);
        sumB += __shfl_xor_sync(0xffffffffu, sumB, 2);
        stlA = stlA * cA + sumA; stmA = mnA;
        stlB = stlB * cB + sumB; stmB = mnB;
        #pragma unroll
        for (int n = 0; n < 16; n++) {
            o[n][0] *= cA; o[n][1] *= cA;
            o[n][2] *= cB; o[n][3] *= cB;
        }

        // ---- PV: O += P·V, 3 split terms; P A-frags come straight from regs ----
        #pragma unroll
        for (int kp = 0; kp < 4; kp++) {
            uint32_t ah0 = ph[2*kp][0],   ah1 = ph[2*kp][1];
            uint32_t ah2 = ph[2*kp+1][0], ah3 = ph[2*kp+1][1];
            uint32_t al0 = pl[2*kp][0],   al1 = pl[2*kp][1];
            uint32_t al2 = pl[2*kp+1][0], al3 = pl[2*kp+1][1];
            #pragma unroll
            for (int db = 0; db < 8; db++) {
                uint32_t bh[4], bl[4];
                uint32_t off = (uint32_t)(kp * 16 * VP + db * 16) * 2;
                ldsm4t(bh, vhi_b + off);
                ldsm4t(bl, vlo_b + off);
                mma16816(o[2*db][0], o[2*db][1], o[2*db][2], o[2*db][3],
                         ah0, ah1, ah2, ah3, bh[0], bh[1]);
                mma16816(o[2*db+1][0], o[2*db+1][1], o[2*db+1][2], o[2*db+1][3],
                         ah0, ah1, ah2, ah3, bh[2], bh[3]);
                mma16816(o[2*db][0], o[2*db][1], o[2*db][2], o[2*db][3],
                         al0, al1, al2, al3, bh[0], bh[1]);
                mma16816(o[2*db+1][0], o[2*db+1][1], o[2*db+1][2], o[2*db+1][3],
                         al0, al1, al2, al3, bh[2], bh[3]);
                mma16816(o[2*db][0], o[2*db][1], o[2*db][2], o[2*db][3],
                         ah0, ah1, ah2, ah3, bl[0], bl[1]);
                mma16816(o[2*db+1][0], o[2*db+1][1], o[2*db+1][2], o[2*db+1][3],
                         ah0, ah1, ah2, ah3, bl[2], bl[3]);
            }
        }
    }

    // ---- write partials ----
    const int pidx = (k * NCHUNK + chunk) * 2 + phalf;
    const int rA = mtile * 16 + (lane >> 2);
    const int rB = rA + 8;
    const int cb = 2 * (lane & 3);
    float* accb = g_acc + (size_t)pidx * ROWS * HD;
    #pragma unroll
    for (int n = 0; n < 16; n++) {
        *(float2*)(accb + rA * HD + n * 8 + cb) = make_float2(o[n][0], o[n][1]);
        *(float2*)(accb + rB * HD + n * 8 + cb) = make_float2(o[n][2], o[n][3]);
    }
    if ((lane & 3) == 0) {
        g_m[pidx * ROWS + rA] = stmA; g_l[pidx * ROWS + rA] = stlA;
        g_m[pidx * ROWS + rB] = stmB; g_l[pidx * ROWS + rB] = stlB;
    }
}

// ---------------------------------------------------------------------------
// Kernel 2: merge the 74 partials per (kv head, row) -> head_outs
// ---------------------------------------------------------------------------
#define NPC (NCHUNK * 2)   // 74 partials per head
__global__ void attn_reduce(float* __restrict__ out)
{
    const int row = blockIdx.x;
    const int k   = blockIdx.y;
    const int d   = threadIdx.x;

    __shared__ float s_m[NPC], s_l[NPC];
    if (d < NPC) {
        s_m[d] = g_m[(k * NPC + d) * ROWS + row];
        s_l[d] = g_l[(k * NPC + d) * ROWS + row];
    }
    __syncthreads();

    float M = NEGINF;
    #pragma unroll 8
    for (int c = 0; c < NPC; c++) M = fmaxf(M, s_m[c]);

    float L = 0.f, acc = 0.f;
    for (int c = 0; c < NPC; c++) {
        float wgt = __expf(s_m[c] - M);
        L += s_l[c] * wgt;
        acc += wgt * g_acc[((size_t)(k * NPC + c) * ROWS + row) * HD + d];
    }
    out[((size_t)k * ROWS + row) * HD + d] = acc / L;
}

// ---------------------------------------------------------------------------
// Kernel 3: scaled_keys / scaled_values outputs
// ---------------------------------------------------------------------------
__global__ void prep_kv(const float* __restrict__ keys,
                        const float* __restrict__ values,
                        const float* __restrict__ kq_scale,
                        float* __restrict__ out_sk,
                        float* __restrict__ out_sv)
{
    int i = blockIdx.x * blockDim.x + threadIdx.x;
    if (i < NKV * BQ * HD) {
        out_sk[i] = keys[i] * kq_scale[0];
        out_sv[i] = fmaxf(values[i], -10000.f);
    }
}

extern "C" void kernel_launch(void* const* d_in, const int* in_sizes, int n_in,
                              void* d_out, int out_size)
{
    const float* q     = (const float*)d_in[0];
    const float* keys  = (const float*)d_in[1];
    const float* ktc   = (const float*)d_in[2];
    const float* vals  = (const float*)d_in[3];
    const float* vc    = (const float*)d_in[4];
    // d_in[5] = attn_bias: only masks the pad tail, handled analytically
    const float* scale = (const float*)d_in[6];
    float* out = (float*)d_out;

    cudaFuncSetAttribute(attn_mma,
                         cudaFuncAttributeMaxDynamicSharedMemorySize, SMEM_BYTES);

    attn_mma<<<dim3(NCHUNK, NKV), 256, SMEM_BYTES>>>(q, keys, ktc, vals, vc, scale);
    attn_reduce<<<dim3(ROWS, NKV), HD>>>(out);

    const int HEAD_OUT = NH * BQ * HD;        // 65536
    const int KV_OUT   = NKV * BQ * HD;       // 16384
    if (out_size >= HEAD_OUT + 2 * KV_OUT) {
        prep_kv<<<64, 256>>>(keys, vals, scale,
                             out + HEAD_OUT, out + HEAD_OUT + KV_OUT);
    }
}

// round 7
// speedup vs baseline: 2.6646x; 1.3198x over previous
#include <cuda_runtime.h>
#include <cuda_bf16.h>
#include <cstdint>

// ---------------- problem constants ----------------
#define NKV    8
#define GRP    4
#define NH     32
#define BQ     16
#define HD     128
#define CACHE  32736
#define KVLEN  32752              // CACHE + BQ; pos >= KVLEN fully masked
#define ROWS   64                 // GRP*BQ query rows per kv head
#define TPOS   64                 // positions per tile
#define NTILES 512                // 512*64 = 32768 >= KVLEN (tile 511 partial)
#define NCHUNK 37                 // 37*8 = 296 CTAs = 2 exact waves
#define TPC    14                 // tiles per chunk (37*14 = 518 >= 512)
#define NPART  (NKV*NCHUNK*2)     // 592 partials (2 pos-halves)
#define NEGINF (-1e30f)

// pitches (bf16 elems)
#define QP 136
#define KP 72
#define VP 136

// smem byte offsets
#define QHI_OFF  0
#define QLO_OFF  (QHI_OFF + ROWS*QP*2)        // 17408
#define KHI_OFF  (QLO_OFF + ROWS*QP*2)        // 34816
#define KLO_OFF  (KHI_OFF + HD*KP*2)          // 53248
#define VHI_OFF  (KLO_OFF + HD*KP*2)          // 71680
#define VLO_OFF  (VHI_OFF + TPOS*VP*2)        // 89088
#define STGK_OFF (VLO_OFF + TPOS*VP*2)        // 106496
#define STGV_OFF (STGK_OFF + HD*TPOS*4)       // 139264
#define SMEM_BYTES (STGV_OFF + TPOS*HD*4)     // 172032

// split-KV scratch (no cudaMalloc -> __device__ globals)
__device__ float g_acc[(size_t)NPART * ROWS * HD];   // ~19.4 MB
__device__ float g_m[NPART * ROWS];
__device__ float g_l[NPART * ROWS];

// ---------------- PTX helpers ----------------
__device__ __forceinline__ void ldsm4(uint32_t r[4], uint32_t a) {
    asm volatile("ldmatrix.sync.aligned.m8n8.x4.shared.b16 {%0,%1,%2,%3},[%4];"
                 : "=r"(r[0]), "=r"(r[1]), "=r"(r[2]), "=r"(r[3]) : "r"(a));
}
__device__ __forceinline__ void ldsm4t(uint32_t r[4], uint32_t a) {
    asm volatile("ldmatrix.sync.aligned.m8n8.x4.trans.shared.b16 {%0,%1,%2,%3},[%4];"
                 : "=r"(r[0]), "=r"(r[1]), "=r"(r[2]), "=r"(r[3]) : "r"(a));
}
__device__ __forceinline__ void mma16816(float& c0, float& c1, float& c2, float& c3,
                                         uint32_t a0, uint32_t a1, uint32_t a2, uint32_t a3,
                                         uint32_t b0, uint32_t b1) {
    asm volatile("mma.sync.aligned.m16n8k16.row.col.f32.bf16.bf16.f32 "
                 "{%0,%1,%2,%3},{%4,%5,%6,%7},{%8,%9},{%0,%1,%2,%3};"
                 : "+f"(c0), "+f"(c1), "+f"(c2), "+f"(c3)
                 : "r"(a0), "r"(a1), "r"(a2), "r"(a3), "r"(b0), "r"(b1));
}
__device__ __forceinline__ uint32_t pk(__nv_bfloat16 a, __nv_bfloat16 b) {
    return (uint32_t)__bfloat16_as_ushort(a) | ((uint32_t)__bfloat16_as_ushort(b) << 16);
}
__device__ __forceinline__ void cvt_hl(float f, __nv_bfloat16& h, __nv_bfloat16& l) {
    h = __float2bfloat16_rn(f);
    l = __float2bfloat16_rn(f - __bfloat162float(h));
}
__device__ __forceinline__ void store_hl4(__nv_bfloat16* hp, __nv_bfloat16* lp, float4 v) {
    __nv_bfloat16 h0, h1, h2, h3, l0, l1, l2, l3;
    cvt_hl(v.x, h0, l0); cvt_hl(v.y, h1, l1);
    cvt_hl(v.z, h2, l2); cvt_hl(v.w, h3, l3);
    *(uint2*)hp = make_uint2(pk(h0, h1), pk(h2, h3));
    *(uint2*)lp = make_uint2(pk(l0, l1), pk(l2, l3));
}
__device__ __forceinline__ void cp16(uint32_t dst, const float* src) {
    asm volatile("cp.async.cg.shared.global [%0],[%1],16;" :: "r"(dst), "l"(src));
}

// ---------------------------------------------------------------------------
// Kernel 1: pipelined tensor-core partial flash attention.
// grid (NCHUNK, NKV), 256 threads (8 warps): mtile = w&3 (16 rows), phalf = w>>2
// (32-pos half). cp.async prefetches next tile's fp32 K/V during compute.
// ---------------------------------------------------------------------------
__global__ void __launch_bounds__(256, 1)
attn_mma(const float* __restrict__ q,
         const float* __restrict__ keys,
         const float* __restrict__ kT,
         const float* __restrict__ values,
         const float* __restrict__ vc,
         const float* __restrict__ kq_scale)
{
    extern __shared__ char smc[];
    __nv_bfloat16* qhi = (__nv_bfloat16*)(smc + QHI_OFF);
    __nv_bfloat16* qlo = (__nv_bfloat16*)(smc + QLO_OFF);
    __nv_bfloat16* khi = (__nv_bfloat16*)(smc + KHI_OFF);
    __nv_bfloat16* klo = (__nv_bfloat16*)(smc + KLO_OFF);
    __nv_bfloat16* vhi = (__nv_bfloat16*)(smc + VHI_OFF);
    __nv_bfloat16* vlo = (__nv_bfloat16*)(smc + VLO_OFF);
    float* stgK = (float*)(smc + STGK_OFF);
    float* stgV = (float*)(smc + STGV_OFF);

    const int chunk = blockIdx.x;
    const int k     = blockIdx.y;
    const int tid   = threadIdx.x;
    const int lane  = tid & 31;
    const int w     = tid >> 5;
    const int mtile = w & 3;
    const int phalf = w >> 2;
    const float scale = kq_scale[0];

    const uint32_t smem_b = (uint32_t)__cvta_generic_to_shared(smc);
    const uint32_t stgK_b = smem_b + STGK_OFF;
    const uint32_t stgV_b = smem_b + STGV_OFF;

    const int t0 = chunk * TPC;
    int t1 = t0 + TPC; if (t1 > NTILES) t1 = NTILES;

    // ---- prefetch first tile (always clean: max t0 pos = 32256+64 <= CACHE) ----
    {
        const int pos0 = t0 * TPOS;
        #pragma unroll
        for (int i = 0; i < 8; i++) {
            int idx = tid + i * 256;  int d = idx >> 4, u = idx & 15;
            cp16(stgK_b + (uint32_t)(d * TPOS + u * 4) * 4,
                 kT + ((size_t)k * HD + d) * CACHE + pos0 + u * 4);
        }
        #pragma unroll
        for (int i = 0; i < 8; i++) {
            int idx = tid + i * 256;  int p = idx >> 5, u = idx & 31;
            cp16(stgV_b + (uint32_t)(p * HD + u * 4) * 4,
                 vc + ((size_t)k * CACHE + pos0 + p) * HD + u * 4);
        }
        asm volatile("cp.async.commit_group;");
    }

    // ---- Q load + hi/lo convert (overlaps with in-flight cp.async) ----
    {
        const float4* qg = (const float4*)(q + (size_t)k * ROWS * HD);
        #pragma unroll
        for (int i = 0; i < 8; i++) {
            int idx = tid + i * 256;  int r = idx >> 5, f = (idx & 31) * 4;
            store_hl4(qhi + r * QP + f, qlo + r * QP + f, qg[idx]);
        }
    }
    __syncthreads();

    const int lrow = lane & 15;
    const int lcol = (lane >> 4) * 8;
    const uint32_t qhi_b = smem_b + QHI_OFF + (uint32_t)((mtile*16 + lrow) * QP + lcol) * 2;
    const uint32_t qlo_b = smem_b + QLO_OFF + (uint32_t)((mtile*16 + lrow) * QP + lcol) * 2;
    const uint32_t khi_b = smem_b + KHI_OFF + (uint32_t)(lrow * KP + phalf * 32 + lcol) * 2;
    const uint32_t klo_b = smem_b + KLO_OFF + (uint32_t)(lrow * KP + phalf * 32 + lcol) * 2;
    const uint32_t vhi_b = smem_b + VHI_OFF + (uint32_t)((phalf*32 + lrow) * VP + lcol) * 2;
    const uint32_t vlo_b = smem_b + VLO_OFF + (uint32_t)((phalf*32 + lrow) * VP + lcol) * 2;

    // hoist Q-hi A-frags for the whole kernel (Q is tile-invariant)
    uint32_t qh[8][4];
    #pragma unroll
    for (int ks = 0; ks < 8; ks++) ldsm4(qh[ks], qhi_b + ks * 32);

    float o[16][4];
    #pragma unroll
    for (int n = 0; n < 16; n++)
        #pragma unroll
        for (int j = 0; j < 4; j++) o[n][j] = 0.f;
    float stmA = NEGINF, stmB = NEGINF, stlA = 0.f, stlB = 0.f;

    for (int t = t0; t < t1; t++) {
        const int pos0 = t * TPOS;
        const bool clean = (pos0 + TPOS <= CACHE);

        if (clean) {
            asm volatile("cp.async.wait_group 0;");
            __syncthreads();           // staging ready AND prev compute done

            // convert fp32 staging -> bf16 hi/lo tiles
            #pragma unroll
            for (int i = 0; i < 8; i++) {
                int idx = tid + i * 256;  int d = idx >> 4, c = (idx & 15) * 4;
                float4 v4 = *(const float4*)(stgK + d * TPOS + c);
                store_hl4(khi + d * KP + c, klo + d * KP + c, v4);
            }
            #pragma unroll
            for (int i = 0; i < 8; i++) {
                int idx = tid + i * 256;  int p = idx >> 5, c = (idx & 31) * 4;
                float4 v4 = *(const float4*)(stgV + p * HD + c);
                store_hl4(vhi + p * VP + c, vlo + p * VP + c, v4);
            }
            __syncthreads();           // bf16 ready; staging dead

            // prefetch next tile (if clean) — flies during compute below
            const int tn = t + 1;
            if (tn < t1 && tn * TPOS + TPOS <= CACHE) {
                const int pn = tn * TPOS;
                #pragma unroll
                for (int i = 0; i < 8; i++) {
                    int idx = tid + i * 256;  int d = idx >> 4, u = idx & 15;
                    cp16(stgK_b + (uint32_t)(d * TPOS + u * 4) * 4,
                         kT + ((size_t)k * HD + d) * CACHE + pn + u * 4);
                }
                #pragma unroll
                for (int i = 0; i < 8; i++) {
                    int idx = tid + i * 256;  int p = idx >> 5, u = idx & 31;
                    cp16(stgV_b + (uint32_t)(p * HD + u * 4) * 4,
                         vc + ((size_t)k * CACHE + pn + p) * HD + u * 4);
                }
                asm volatile("cp.async.commit_group;");
            }
        } else {
            // tail tile (t=511 only): predicated scalar load, no cp.async
            __syncthreads();
            #pragma unroll 4
            for (int i = 0; i < 32; i++) {
                int idx = tid + i * 256;  int d = idx >> 6, p = idx & 63;
                int gp = pos0 + p;  float f = 0.f;
                if (gp < CACHE)      f = kT[((size_t)k * HD + d) * CACHE + gp];
                else if (gp < KVLEN) f = keys[(k * BQ + (gp - CACHE)) * HD + d] * scale;
                __nv_bfloat16 h, l; cvt_hl(f, h, l);
                khi[d * KP + p] = h;  klo[d * KP + p] = l;
            }
            #pragma unroll 4
            for (int i = 0; i < 32; i++) {
                int idx = tid + i * 256;  int p = idx >> 7, d = idx & 127;
                int gp = pos0 + p;  float f = 0.f;
                if (gp < CACHE)      f = vc[((size_t)k * CACHE + gp) * HD + d];
                else if (gp < KVLEN) f = fmaxf(values[(k * BQ + (gp - CACHE)) * HD + d], -10000.f);
                __nv_bfloat16 h, l; cvt_hl(f, h, l);
                vhi[p * VP + d] = h;  vlo[p * VP + d] = l;
            }
            __syncthreads();
        }

        // ---- QK: S[16 rows][32 pos], 3 split terms, K-hi frags reused ----
        float s[4][4];
        #pragma unroll
        for (int n = 0; n < 4; n++)
            #pragma unroll
            for (int j = 0; j < 4; j++) s[n][j] = 0.f;

        #pragma unroll
        for (int ks = 0; ks < 8; ks++) {
            uint32_t b0[4], b1[4], a[4];
            ldsm4t(b0, khi_b + (uint32_t)(ks * 16 * KP) * 2);
            ldsm4t(b1, khi_b + (uint32_t)(ks * 16 * KP + 16) * 2);
            // hi * hi
            mma16816(s[0][0],s[0][1],s[0][2],s[0][3], qh[ks][0],qh[ks][1],qh[ks][2],qh[ks][3], b0[0],b0[1]);
            mma16816(s[1][0],s[1][1],s[1][2],s[1][3], qh[ks][0],qh[ks][1],qh[ks][2],qh[ks][3], b0[2],b0[3]);
            mma16816(s[2][0],s[2][1],s[2][2],s[2][3], qh[ks][0],qh[ks][1],qh[ks][2],qh[ks][3], b1[0],b1[1]);
            mma16816(s[3][0],s[3][1],s[3][2],s[3][3], qh[ks][0],qh[ks][1],qh[ks][2],qh[ks][3], b1[2],b1[3]);
            // lo(Q) * hi(K) — reuse b0/b1
            ldsm4(a, qlo_b + ks * 32);
            mma16816(s[0][0],s[0][1],s[0][2],s[0][3], a[0],a[1],a[2],a[3], b0[0],b0[1]);
            mma16816(s[1][0],s[1][1],s[1][2],s[1][3], a[0],a[1],a[2],a[3], b0[2],b0[3]);
            mma16816(s[2][0],s[2][1],s[2][2],s[2][3], a[0],a[1],a[2],a[3], b1[0],b1[1]);
            mma16816(s[3][0],s[3][1],s[3][2],s[3][3], a[0],a[1],a[2],a[3], b1[2],b1[3]);
            // hi(Q) * lo(K)
            ldsm4t(b0, klo_b + (uint32_t)(ks * 16 * KP) * 2);
            ldsm4t(b1, klo_b + (uint32_t)(ks * 16 * KP + 16) * 2);
            mma16816(s[0][0],s[0][1],s[0][2],s[0][3], qh[ks][0],qh[ks][1],qh[ks][2],qh[ks][3], b0[0],b0[1]);
            mma16816(s[1][0],s[1][1],s[1][2],s[1][3], qh[ks][0],qh[ks][1],qh[ks][2],qh[ks][3], b0[2],b0[3]);
            mma16816(s[2][0],s[2][1],s[2][2],s[2][3], qh[ks][0],qh[ks][1],qh[ks][2],qh[ks][3], b1[0],b1[1]);
            mma16816(s[3][0],s[3][1],s[3][2],s[3][3], qh[ks][0],qh[ks][1],qh[ks][2],qh[ks][3], b1[2],b1[3]);
        }

        // ---- mask pad positions (tail tile only) ----
        if (pos0 + TPOS > KVLEN) {
            int cbase = pos0 + phalf * 32 + 2 * (lane & 3);
            #pragma unroll
            for (int n = 0; n < 4; n++) {
                if (cbase + n * 8     >= KVLEN) { s[n][0] = NEGINF; s[n][2] = NEGINF; }
                if (cbase + n * 8 + 1 >= KVLEN) { s[n][1] = NEGINF; s[n][3] = NEGINF; }
            }
        }

        // ---- online softmax (rows rA = lane>>2, rB = rA+8) ----
        float mxA = NEGINF, mxB = NEGINF;
        #pragma unroll
        for (int n = 0; n < 4; n++) {
            mxA = fmaxf(mxA, fmaxf(s[n][0], s[n][1]));
            mxB = fmaxf(mxB, fmaxf(s[n][2], s[n][3]));
        }
        mxA = fmaxf(mxA, __shfl_xor_sync(0xffffffffu, mxA, 1));
        mxA = fmaxf(mxA, __shfl_xor_sync(0xffffffffu, mxA, 2));
        mxB = fmaxf(mxB, __shfl_xor_sync(0xffffffffu, mxB, 1));
        mxB = fmaxf(mxB, __shfl_xor_sync(0xffffffffu, mxB, 2));
        float mnA = fmaxf(stmA, mxA), mnB = fmaxf(stmB, mxB);
        float cA = __expf(stmA - mnA), cB = __expf(stmB - mnB);

        uint32_t ph[4][2], pl[4][2];
        float sumA = 0.f, sumB = 0.f;
        #pragma unroll
        for (int n = 0; n < 4; n++) {
            float p0 = __expf(s[n][0] - mnA), p1 = __expf(s[n][1] - mnA);
            float p2 = __expf(s[n][2] - mnB), p3 = __expf(s[n][3] - mnB);
            sumA += p0 + p1;  sumB += p2 + p3;
            __nv_bfloat16 h0, h1, h2, h3, l0, l1, l2, l3;
            cvt_hl(p0, h0, l0); cvt_hl(p1, h1, l1);
            cvt_hl(p2, h2, l2); cvt_hl(p3, h3, l3);
            ph[n][0] = pk(h0, h1);  ph[n][1] = pk(h2, h3);
            pl[n][0] = pk(l0, l1);  pl[n][1] = pk(l2, l3);
        }
        sumA += __shfl_xor_sync(0xffffffffu, sumA, 1);
        sumA += __shfl_xor_sync(0xffffffffu, sumA, 2);
        sumB += __shfl_xor_sync(0xffffffffu, sumB, 1);
        sumB += __shfl_xor_sync(0xffffffffu, sumB, 2);
        stlA = stlA * cA + sumA;  stmA = mnA;
        stlB = stlB * cB + sumB;  stmB = mnB;
        #pragma unroll
        for (int n = 0; n < 16; n++) {
            o[n][0] *= cA; o[n][1] *= cA;
            o[n][2] *= cB; o[n][3] *= cB;
        }

        // ---- PV: O += P*V (K-dim = 32 positions of this phalf) ----
        #pragma unroll
        for (int kp = 0; kp < 2; kp++) {
            uint32_t ah0 = ph[2*kp][0],   ah1 = ph[2*kp][1];
            uint32_t ah2 = ph[2*kp+1][0], ah3 = ph[2*kp+1][1];
            uint32_t al0 = pl[2*kp][0],   al1 = pl[2*kp][1];
            uint32_t al2 = pl[2*kp+1][0], al3 = pl[2*kp+1][1];
            #pragma unroll
            for (int db = 0; db < 8; db++) {
                uint32_t bh[4], bl[4];
                uint32_t off = (uint32_t)(kp * 16 * VP + db * 16) * 2;
                ldsm4t(bh, vhi_b + off);
                ldsm4t(bl, vlo_b + off);
                mma16816(o[2*db][0], o[2*db][1], o[2*db][2], o[2*db][3],
                         ah0, ah1, ah2, ah3, bh[0], bh[1]);
                mma16816(o[2*db+1][0], o[2*db+1][1], o[2*db+1][2], o[2*db+1][3],
                         ah0, ah1, ah2, ah3, bh[2], bh[3]);
                mma16816(o[2*db][0], o[2*db][1], o[2*db][2], o[2*db][3],
                         al0, al1, al2, al3, bh[0], bh[1]);
                mma16816(o[2*db+1][0], o[2*db+1][1], o[2*db+1][2], o[2*db+1][3],
                         al0, al1, al2, al3, bh[2], bh[3]);
                mma16816(o[2*db][0], o[2*db][1], o[2*db][2], o[2*db][3],
                         ah0, ah1, ah2, ah3, bl[0], bl[1]);
                mma16816(o[2*db+1][0], o[2*db+1][1], o[2*db+1][2], o[2*db+1][3],
                         ah0, ah1, ah2, ah3, bl[2], bl[3]);
            }
        }
    }

    // ---- write partials ----
    const int pidx = (k * NCHUNK + chunk) * 2 + phalf;
    const int rA = mtile * 16 + (lane >> 2);
    const int rB = rA + 8;
    const int cb = 2 * (lane & 3);
    float* accb = g_acc + (size_t)pidx * ROWS * HD;
    #pragma unroll
    for (int n = 0; n < 16; n++) {
        *(float2*)(accb + rA * HD + n * 8 + cb) = make_float2(o[n][0], o[n][1]);
        *(float2*)(accb + rB * HD + n * 8 + cb) = make_float2(o[n][2], o[n][3]);
    }
    if ((lane & 3) == 0) {
        g_m[pidx * ROWS + rA] = stmA;  g_l[pidx * ROWS + rA] = stlA;
        g_m[pidx * ROWS + rB] = stmB;  g_l[pidx * ROWS + rB] = stlB;
    }
}

// ---------------------------------------------------------------------------
// Kernel 2: merge the 74 partials per (kv head, row) -> head_outs
// ---------------------------------------------------------------------------
#define NPC (NCHUNK * 2)   // 74 partials per head
__global__ void attn_reduce(float* __restrict__ out)
{
    const int row = blockIdx.x;
    const int k   = blockIdx.y;
    const int d   = threadIdx.x;

    __shared__ float s_m[NPC], s_l[NPC];
    if (d < NPC) {
        s_m[d] = g_m[(k * NPC + d) * ROWS + row];
        s_l[d] = g_l[(k * NPC + d) * ROWS + row];
    }
    __syncthreads();

    float M = NEGINF;
    #pragma unroll 8
    for (int c = 0; c < NPC; c++) M = fmaxf(M, s_m[c]);

    float L = 0.f, acc = 0.f;
    for (int c = 0; c < NPC; c++) {
        float wgt = __expf(s_m[c] - M);
        L += s_l[c] * wgt;
        acc += wgt * g_acc[((size_t)(k * NPC + c) * ROWS + row) * HD + d];
    }
    out[((size_t)k * ROWS + row) * HD + d] = acc / L;
}

// ---------------------------------------------------------------------------
// Kernel 3: scaled_keys / scaled_values outputs
// ---------------------------------------------------------------------------
__global__ void prep_kv(const float* __restrict__ keys,
                        const float* __restrict__ values,
                        const float* __restrict__ kq_scale,
                        float* __restrict__ out_sk,
                        float* __restrict__ out_sv)
{
    int i = blockIdx.x * blockDim.x + threadIdx.x;
    if (i < NKV * BQ * HD) {
        out_sk[i] = keys[i] * kq_scale[0];
        out_sv[i] = fmaxf(values[i], -10000.f);
    }
}

extern "C" void kernel_launch(void* const* d_in, const int* in_sizes, int n_in,
                              void* d_out, int out_size)
{
    const float* q     = (const float*)d_in[0];
    const float* keys  = (const float*)d_in[1];
    const float* ktc   = (const float*)d_in[2];
    const float* vals  = (const float*)d_in[3];
    const float* vc    = (const float*)d_in[4];
    // d_in[5] = attn_bias: only masks the pad tail, handled analytically
    const float* scale = (const float*)d_in[6];
    float* out = (float*)d_out;

    cudaFuncSetAttribute(attn_mma,
                         cudaFuncAttributeMaxDynamicSharedMemorySize, SMEM_BYTES);

    attn_mma<<<dim3(NCHUNK, NKV), 256, SMEM_BYTES>>>(q, keys, ktc, vals, vc, scale);
    attn_reduce<<<dim3(ROWS, NKV), HD>>>(out);

    const int HEAD_OUT = NH * BQ * HD;        // 65536
    const int KV_OUT   = NKV * BQ * HD;       // 16384
    if (out_size >= HEAD_OUT + 2 * KV_OUT) {
        prep_kv<<<64, 256>>>(keys, vals, scale,
                             out + HEAD_OUT, out + HEAD_OUT + KV_OUT);
    }
}

// round 12
// speedup vs baseline: 3.2448x; 1.2177x over previous
#include <cuda_runtime.h>
#include <cuda_bf16.h>
#include <cstdint>

// ---------------- problem constants ----------------
#define NKV    8
#define GRP    4
#define NH     32
#define BQ     16
#define HD     128
#define CACHE  32736
#define KVLEN  32752              // CACHE + BQ; pos >= KVLEN fully masked
#define ROWS   64                 // GRP*BQ query rows per kv head
#define TPOS   32                 // positions per tile
#define NTILES 1024               // 1024*32 = 32768 >= KVLEN (tile 1023 = new keys+pad)
#define NCHUNK 37                 // 37*8 = 296 CTAs = one resident wave @2 CTA/SM
#define TPC    28                 // tiles per chunk (37*28 = 1036 >= 1024)
#define NPART  (NKV*NCHUNK)       // 296 partials
#define NEGINF (-1e30f)

// pitches (bf16 elems)
#define QP 136
#define KP 40                     // 80B row stride: 5 (mod 8) 16B units -> LDSM conflict-free
#define VP 136

// smem byte offsets (total 105472 -> 2 CTAs/SM)
#define QLO_OFF  0
#define KHI_OFF  (QLO_OFF + ROWS*QP*2)        // 17408
#define KLO_OFF  (KHI_OFF + HD*KP*2)          // 27648
#define VHI_OFF  (KLO_OFF + HD*KP*2)          // 37888
#define VLO_OFF  (VHI_OFF + TPOS*VP*2)        // 46592
#define STGK_OFF (VLO_OFF + TPOS*VP*2)        // 55296
#define STGV_OFF (STGK_OFF + HD*TPOS*4)       // 71680
#define QHI_OFF  (STGV_OFF + TPOS*HD*4)       // 88064 (prologue only)
#define SMEM_BYTES (QHI_OFF + ROWS*QP*2)      // 105472

// split-KV scratch (no cudaMalloc -> __device__ globals)
__device__ float g_acc[(size_t)NPART * ROWS * HD];   // ~9.7 MB
__device__ float g_m[NPART * ROWS];
__device__ float g_l[NPART * ROWS];

// ---------------- PTX helpers ----------------
__device__ __forceinline__ void ldsm4(uint32_t r[4], uint32_t a) {
    asm volatile("ldmatrix.sync.aligned.m8n8.x4.shared.b16 {%0,%1,%2,%3},[%4];"
                 : "=r"(r[0]), "=r"(r[1]), "=r"(r[2]), "=r"(r[3]) : "r"(a));
}
__device__ __forceinline__ void ldsm4t(uint32_t r[4], uint32_t a) {
    asm volatile("ldmatrix.sync.aligned.m8n8.x4.trans.shared.b16 {%0,%1,%2,%3},[%4];"
                 : "=r"(r[0]), "=r"(r[1]), "=r"(r[2]), "=r"(r[3]) : "r"(a));
}
__device__ __forceinline__ void mma16816(float& c0, float& c1, float& c2, float& c3,
                                         uint32_t a0, uint32_t a1, uint32_t a2, uint32_t a3,
                                         uint32_t b0, uint32_t b1) {
    asm volatile("mma.sync.aligned.m16n8k16.row.col.f32.bf16.bf16.f32 "
                 "{%0,%1,%2,%3},{%4,%5,%6,%7},{%8,%9},{%0,%1,%2,%3};"
                 : "+f"(c0), "+f"(c1), "+f"(c2), "+f"(c3)
                 : "r"(a0), "r"(a1), "r"(a2), "r"(a3), "r"(b0), "r"(b1));
}
__device__ __forceinline__ uint32_t pk(__nv_bfloat16 a, __nv_bfloat16 b) {
    return (uint32_t)__bfloat16_as_ushort(a) | ((uint32_t)__bfloat16_as_ushort(b) << 16);
}
__device__ __forceinline__ void cvt_hl(float f, __nv_bfloat16& h, __nv_bfloat16& l) {
    h = __float2bfloat16_rn(f);
    l = __float2bfloat16_rn(f - __bfloat162float(h));
}
__device__ __forceinline__ void store_hl4(__nv_bfloat16* hp, __nv_bfloat16* lp, float4 v) {
    __nv_bfloat16 h0, h1, h2, h3, l0, l1, l2, l3;
    cvt_hl(v.x, h0, l0); cvt_hl(v.y, h1, l1);
    cvt_hl(v.z, h2, l2); cvt_hl(v.w, h3, l3);
    *(uint2*)hp = make_uint2(pk(h0, h1), pk(h2, h3));
    *(uint2*)lp = make_uint2(pk(l0, l1), pk(l2, l3));
}
__device__ __forceinline__ void cp16(uint32_t dst, const float* src) {
    asm volatile("cp.async.cg.shared.global [%0],[%1],16;" :: "r"(dst), "l"(src));
}

// ---------------------------------------------------------------------------
// Kernel 1: pipelined tensor-core partial flash attention.
// grid (NCHUNK, NKV), 128 threads (4 warps), 2 CTAs/SM for phase overlap:
// while one CTA sits in cp.async.wait/convert/barrier, the co-resident CTA's
// warps feed the tensor pipe. warp w = mtile (16 rows), full 32-pos tile/warp.
// ---------------------------------------------------------------------------
__global__ void __launch_bounds__(128, 2)
attn_mma(const float* __restrict__ q,
         const float* __restrict__ keys,
         const float* __restrict__ kT,
         const float* __restrict__ values,
         const float* __restrict__ vc,
         const float* __restrict__ kq_scale)
{
    extern __shared__ char smc[];
    __nv_bfloat16* qhi = (__nv_bfloat16*)(smc + QHI_OFF);
    __nv_bfloat16* qlo = (__nv_bfloat16*)(smc + QLO_OFF);
    __nv_bfloat16* khi = (__nv_bfloat16*)(smc + KHI_OFF);
    __nv_bfloat16* klo = (__nv_bfloat16*)(smc + KLO_OFF);
    __nv_bfloat16* vhi = (__nv_bfloat16*)(smc + VHI_OFF);
    __nv_bfloat16* vlo = (__nv_bfloat16*)(smc + VLO_OFF);
    float* stgK = (float*)(smc + STGK_OFF);
    float* stgV = (float*)(smc + STGV_OFF);

    const int chunk = blockIdx.x;
    const int k     = blockIdx.y;
    const int tid   = threadIdx.x;
    const int lane  = tid & 31;
    const int mtile = tid >> 5;          // warp id = mtile
    const float scale = kq_scale[0];

    const uint32_t smem_b = (uint32_t)__cvta_generic_to_shared(smc);
    const uint32_t stgK_b = smem_b + STGK_OFF;
    const uint32_t stgV_b = smem_b + STGV_OFF;

    const int t0 = chunk * TPC;
    int t1 = t0 + TPC; if (t1 > NTILES) t1 = NTILES;

    // ---- prefetch first tile (always clean: max t0 = 1008 -> pos 32256+32 <= CACHE) ----
    {
        const int pos0 = t0 * TPOS;
        #pragma unroll
        for (int i = 0; i < 8; i++) {               // K: 1024 float4
            int idx = tid + i * 128;  int d = idx >> 3, u = idx & 7;
            cp16(stgK_b + (uint32_t)(d * TPOS + u * 4) * 4,
                 kT + ((size_t)k * HD + d) * CACHE + pos0 + u * 4);
        }
        #pragma unroll
        for (int i = 0; i < 8; i++) {               // V: 1024 float4
            int idx = tid + i * 128;  int p = idx >> 5, u = idx & 31;
            cp16(stgV_b + (uint32_t)(p * HD + u * 4) * 4,
                 vc + ((size_t)k * CACHE + pos0 + p) * HD + u * 4);
        }
        asm volatile("cp.async.commit_group;");
    }

    // ---- Q load + hi/lo convert (overlaps with in-flight cp.async) ----
    {
        const float4* qg = (const float4*)(q + (size_t)k * ROWS * HD);
        #pragma unroll
        for (int i = 0; i < 16; i++) {
            int idx = tid + i * 128;  int r = idx >> 5, f = (idx & 31) * 4;
            store_hl4(qhi + r * QP + f, qlo + r * QP + f, qg[idx]);
        }
    }
    __syncthreads();

    const int lrow = lane & 15;
    const int lcol = (lane >> 4) * 8;
    const uint32_t qhi_b = smem_b + QHI_OFF + (uint32_t)((mtile*16 + lrow) * QP + lcol) * 2;
    const uint32_t qlo_b = smem_b + QLO_OFF + (uint32_t)((mtile*16 + lrow) * QP + lcol) * 2;
    const uint32_t khi_b = smem_b + KHI_OFF + (uint32_t)(lrow * KP + lcol) * 2;
    const uint32_t klo_b = smem_b + KLO_OFF + (uint32_t)(lrow * KP + lcol) * 2;
    const uint32_t vhi_b = smem_b + VHI_OFF + (uint32_t)(lrow * VP + lcol) * 2;
    const uint32_t vlo_b = smem_b + VLO_OFF + (uint32_t)(lrow * VP + lcol) * 2;

    // hoist Q-hi A-frags for the whole kernel (Q-hi smem dead afterwards)
    uint32_t qh[8][4];
    #pragma unroll
    for (int ks = 0; ks < 8; ks++) ldsm4(qh[ks], qhi_b + ks * 32);

    float o[16][4];
    #pragma unroll
    for (int n = 0; n < 16; n++)
        #pragma unroll
        for (int j = 0; j < 4; j++) o[n][j] = 0.f;
    float stmA = NEGINF, stmB = NEGINF, stlA = 0.f, stlB = 0.f;

    for (int t = t0; t < t1; t++) {
        const int pos0 = t * TPOS;
        const bool clean = (pos0 + TPOS <= CACHE);

        if (clean) {
            asm volatile("cp.async.wait_group 0;");
            __syncthreads();           // staging ready AND prev compute done

            // convert fp32 staging -> bf16 hi/lo tiles
            #pragma unroll
            for (int i = 0; i < 8; i++) {
                int idx = tid + i * 128;  int d = idx >> 3, c = (idx & 7) * 4;
                float4 v4 = *(const float4*)(stgK + d * TPOS + c);
                store_hl4(khi + d * KP + c, klo + d * KP + c, v4);
            }
            #pragma unroll
            for (int i = 0; i < 8; i++) {
                int idx = tid + i * 128;  int p = idx >> 5, c = (idx & 31) * 4;
                float4 v4 = *(const float4*)(stgV + p * HD + c);
                store_hl4(vhi + p * VP + c, vlo + p * VP + c, v4);
            }
            __syncthreads();           // bf16 ready; staging dead

            // prefetch next tile (if clean) — flies during compute below
            const int tn = t + 1;
            if (tn < t1 && tn * TPOS + TPOS <= CACHE) {
                const int pn = tn * TPOS;
                #pragma unroll
                for (int i = 0; i < 8; i++) {
                    int idx = tid + i * 128;  int d = idx >> 3, u = idx & 7;
                    cp16(stgK_b + (uint32_t)(d * TPOS + u * 4) * 4,
                         kT + ((size_t)k * HD + d) * CACHE + pn + u * 4);
                }
                #pragma unroll
                for (int i = 0; i < 8; i++) {
                    int idx = tid + i * 128;  int p = idx >> 5, u = idx & 31;
                    cp16(stgV_b + (uint32_t)(p * HD + u * 4) * 4,
                         vc + ((size_t)k * CACHE + pn + p) * HD + u * 4);
                }
                asm volatile("cp.async.commit_group;");
            }
        } else {
            // tail tile (t=1023 only): entirely new keys + pad, scalar predicated
            __syncthreads();
            #pragma unroll 4
            for (int i = 0; i < 32; i++) {
                int idx = tid + i * 128;  int d = idx >> 5, p = idx & 31;
                int gp = pos0 + p;  float f = 0.f;
                if (gp < CACHE)      f = kT[((size_t)k * HD + d) * CACHE + gp];
                else if (gp < KVLEN) f = keys[(k * BQ + (gp - CACHE)) * HD + d] * scale;
                __nv_bfloat16 h, l; cvt_hl(f, h, l);
                khi[d * KP + p] = h;  klo[d * KP + p] = l;
            }
            #pragma unroll 4
            for (int i = 0; i < 32; i++) {
                int idx = tid + i * 128;  int p = idx >> 7, d = idx & 127;
                int gp = pos0 + p;  float f = 0.f;
                if (gp < CACHE)      f = vc[((size_t)k * CACHE + gp) * HD + d];
                else if (gp < KVLEN) f = fmaxf(values[(k * BQ + (gp - CACHE)) * HD + d], -10000.f);
                __nv_bfloat16 h, l; cvt_hl(f, h, l);
                vhi[p * VP + d] = h;  vlo[p * VP + d] = l;
            }
            __syncthreads();
        }

        // ---- QK: S[16 rows][32 pos], 3 split terms, K-hi frags reused ----
        float s[4][4];
        #pragma unroll
        for (int n = 0; n < 4; n++)
            #pragma unroll
            for (int j = 0; j < 4; j++) s[n][j] = 0.f;

        #pragma unroll
        for (int ks = 0; ks < 8; ks++) {
            uint32_t b0[4], b1[4], a[4];
            ldsm4t(b0, khi_b + (uint32_t)(ks * 16 * KP) * 2);
            ldsm4t(b1, khi_b + (uint32_t)(ks * 16 * KP + 16) * 2);
            // hi * hi
            mma16816(s[0][0],s[0][1],s[0][2],s[0][3], qh[ks][0],qh[ks][1],qh[ks][2],qh[ks][3], b0[0],b0[1]);
            mma16816(s[1][0],s[1][1],s[1][2],s[1][3], qh[ks][0],qh[ks][1],qh[ks][2],qh[ks][3], b0[2],b0[3]);
            mma16816(s[2][0],s[2][1],s[2][2],s[2][3], qh[ks][0],qh[ks][1],qh[ks][2],qh[ks][3], b1[0],b1[1]);
            mma16816(s[3][0],s[3][1],s[3][2],s[3][3], qh[ks][0],qh[ks][1],qh[ks][2],qh[ks][3], b1[2],b1[3]);
            // lo(Q) * hi(K) — reuse b0/b1
            ldsm4(a, qlo_b + ks * 32);
            mma16816(s[0][0],s[0][1],s[0][2],s[0][3], a[0],a[1],a[2],a[3], b0[0],b0[1]);
            mma16816(s[1][0],s[1][1],s[1][2],s[1][3], a[0],a[1],a[2],a[3], b0[2],b0[3]);
            mma16816(s[2][0],s[2][1],s[2][2],s[2][3], a[0],a[1],a[2],a[3], b1[0],b1[1]);
            mma16816(s[3][0],s[3][1],s[3][2],s[3][3], a[0],a[1],a[2],a[3], b1[2],b1[3]);
            // hi(Q) * lo(K)
            ldsm4t(b0, klo_b + (uint32_t)(ks * 16 * KP) * 2);
            ldsm4t(b1, klo_b + (uint32_t)(ks * 16 * KP + 16) * 2);
            mma16816(s[0][0],s[0][1],s[0][2],s[0][3], qh[ks][0],qh[ks][1],qh[ks][2],qh[ks][3], b0[0],b0[1]);
            mma16816(s[1][0],s[1][1],s[1][2],s[1][3], qh[ks][0],qh[ks][1],qh[ks][2],qh[ks][3], b0[2],b0[3]);
            mma16816(s[2][0],s[2][1],s[2][2],s[2][3], qh[ks][0],qh[ks][1],qh[ks][2],qh[ks][3], b1[0],b1[1]);
            mma16816(s[3][0],s[3][1],s[3][2],s[3][3], qh[ks][0],qh[ks][1],qh[ks][2],qh[ks][3], b1[2],b1[3]);
        }

        // ---- mask pad positions (tail tile only) ----
        if (pos0 + TPOS > KVLEN) {
            int cbase = pos0 + 2 * (lane & 3);
            #pragma unroll
            for (int n = 0; n < 4; n++) {
                if (cbase + n * 8     >= KVLEN) { s[n][0] = NEGINF; s[n][2] = NEGINF; }
                if (cbase + n * 8 + 1 >= KVLEN) { s[n][1] = NEGINF; s[n][3] = NEGINF; }
            }
        }

        // ---- online softmax (rows rA = lane>>2, rB = rA+8) ----
        float mxA = NEGINF, mxB = NEGINF;
        #pragma unroll
        for (int n = 0; n < 4; n++) {
            mxA = fmaxf(mxA, fmaxf(s[n][0], s[n][1]));
            mxB = fmaxf(mxB, fmaxf(s[n][2], s[n][3]));
        }
        mxA = fmaxf(mxA, __shfl_xor_sync(0xffffffffu, mxA, 1));
        mxA = fmaxf(mxA, __shfl_xor_sync(0xffffffffu, mxA, 2));
        mxB = fmaxf(mxB, __shfl_xor_sync(0xffffffffu, mxB, 1));
        mxB = fmaxf(mxB, __shfl_xor_sync(0xffffffffu, mxB, 2));
        float mnA = fmaxf(stmA, mxA), mnB = fmaxf(stmB, mxB);
        float cA = __expf(stmA - mnA), cB = __expf(stmB - mnB);

        uint32_t ph[4][2], pl[4][2];
        float sumA = 0.f, sumB = 0.f;
        #pragma unroll
        for (int n = 0; n < 4; n++) {
            float p0 = __expf(s[n][0] - mnA), p1 = __expf(s[n][1] - mnA);
            float p2 = __expf(s[n][2] - mnB), p3 = __expf(s[n][3] - mnB);
            sumA += p0 + p1;  sumB += p2 + p3;
            __nv_bfloat16 h0, h1, h2, h3, l0, l1, l2, l3;
            cvt_hl(p0, h0, l0); cvt_hl(p1, h1, l1);
            cvt_hl(p2, h2, l2); cvt_hl(p3, h3, l3);
            ph[n][0] = pk(h0, h1);  ph[n][1] = pk(h2, h3);
            pl[n][0] = pk(l0, l1);  pl[n][1] = pk(l2, l3);
        }
        sumA += __shfl_xor_sync(0xffffffffu, sumA, 1);
        sumA += __shfl_xor_sync(0xffffffffu, sumA, 2);
        sumB += __shfl_xor_sync(0xffffffffu, sumB, 1);
        sumB += __shfl_xor_sync(0xffffffffu, sumB, 2);
        stlA = stlA * cA + sumA;  stmA = mnA;
        stlB = stlB * cB + sumB;  stmB = mnB;
        #pragma unroll
        for (int n = 0; n < 16; n++) {
            o[n][0] *= cA; o[n][1] *= cA;
            o[n][2] *= cB; o[n][3] *= cB;
        }

        // ---- PV: O += P*V over 32 positions ----
        #pragma unroll
        for (int kp = 0; kp < 2; kp++) {
            uint32_t ah0 = ph[2*kp][0],   ah1 = ph[2*kp][1];
            uint32_t ah2 = ph[2*kp+1][0], ah3 = ph[2*kp+1][1];
            uint32_t al0 = pl[2*kp][0],   al1 = pl[2*kp][1];
            uint32_t al2 = pl[2*kp+1][0], al3 = pl[2*kp+1][1];
            #pragma unroll
            for (int db = 0; db < 8; db++) {
                uint32_t bh[4], bl[4];
                uint32_t off = (uint32_t)(kp * 16 * VP + db * 16) * 2;
                ldsm4t(bh, vhi_b + off);
                ldsm4t(bl, vlo_b + off);
                mma16816(o[2*db][0], o[2*db][1], o[2*db][2], o[2*db][3],
                         ah0, ah1, ah2, ah3, bh[0], bh[1]);
                mma16816(o[2*db+1][0], o[2*db+1][1], o[2*db+1][2], o[2*db+1][3],
                         ah0, ah1, ah2, ah3, bh[2], bh[3]);
                mma16816(o[2*db][0], o[2*db][1], o[2*db][2], o[2*db][3],
                         al0, al1, al2, al3, bh[0], bh[1]);
                mma16816(o[2*db+1][0], o[2*db+1][1], o[2*db+1][2], o[2*db+1][3],
                         al0, al1, al2, al3, bh[2], bh[3]);
                mma16816(o[2*db][0], o[2*db][1], o[2*db][2], o[2*db][3],
                         ah0, ah1, ah2, ah3, bl[0], bl[1]);
                mma16816(o[2*db+1][0], o[2*db+1][1], o[2*db+1][2], o[2*db+1][3],
                         ah0, ah1, ah2, ah3, bl[2], bl[3]);
            }
        }
    }

    // ---- write partials ----
    const int pidx = k * NCHUNK + chunk;
    const int rA = mtile * 16 + (lane >> 2);
    const int rB = rA + 8;
    const int cb = 2 * (lane & 3);
    float* accb = g_acc + (size_t)pidx * ROWS * HD;
    #pragma unroll
    for (int n = 0; n < 16; n++) {
        *(float2*)(accb + rA * HD + n * 8 + cb) = make_float2(o[n][0], o[n][1]);
        *(float2*)(accb + rB * HD + n * 8 + cb) = make_float2(o[n][2], o[n][3]);
    }
    if ((lane & 3) == 0) {
        g_m[pidx * ROWS + rA] = stmA;  g_l[pidx * ROWS + rA] = stlA;
        g_m[pidx * ROWS + rB] = stmB;  g_l[pidx * ROWS + rB] = stlB;
    }
}

// ---------------------------------------------------------------------------
// Kernel 2: merge the 37 partials per (kv head, row) -> head_outs
// ---------------------------------------------------------------------------
#define NPC NCHUNK   // 37 partials per head
__global__ void attn_reduce(float* __restrict__ out)
{
    const int row = blockIdx.x;
    const int k   = blockIdx.y;
    const int d   = threadIdx.x;

    __shared__ float s_m[NPC], s_l[NPC];
    if (d < NPC) {
        s_m[d] = g_m[(k * NPC + d) * ROWS + row];
        s_l[d] = g_l[(k * NPC + d) * ROWS + row];
    }
    __syncthreads();

    float M = NEGINF;
    #pragma unroll 8
    for (int c = 0; c < NPC; c++) M = fmaxf(M, s_m[c]);

    float L = 0.f, acc = 0.f;
    for (int c = 0; c < NPC; c++) {
        float wgt = __expf(s_m[c] - M);
        L += s_l[c] * wgt;
        acc += wgt * g_acc[((size_t)(k * NPC + c) * ROWS + row) * HD + d];
    }
    out[((size_t)k * ROWS + row) * HD + d] = acc / L;
}

// ---------------------------------------------------------------------------
// Kernel 3: scaled_keys / scaled_values outputs
// ---------------------------------------------------------------------------
__global__ void prep_kv(const float* __restrict__ keys,
                        const float* __restrict__ values,
                        const float* __restrict__ kq_scale,
                        float* __restrict__ out_sk,
                        float* __restrict__ out_sv)
{
    int i = blockIdx.x * blockDim.x + threadIdx.x;
    if (i < NKV * BQ * HD) {
        out_sk[i] = keys[i] * kq_scale[0];
        out_sv[i] = fmaxf(values[i], -10000.f);
    }
}

extern "C" void kernel_launch(void* const* d_in, const int* in_sizes, int n_in,
                              void* d_out, int out_size)
{
    const float* q     = (const float*)d_in[0];
    const float* keys  = (const float*)d_in[1];
    const float* ktc   = (const float*)d_in[2];
    const float* vals  = (const float*)d_in[3];
    const float* vc    = (const float*)d_in[4];
    // d_in[5] = attn_bias: only masks the pad tail, handled analytically
    const float* scale = (const float*)d_in[6];
    float* out = (float*)d_out;

    cudaFuncSetAttribute(attn_mma,
                         cudaFuncAttributeMaxDynamicSharedMemorySize, SMEM_BYTES);

    attn_mma<<<dim3(NCHUNK, NKV), 128, SMEM_BYTES>>>(q, keys, ktc, vals, vc, scale);
    attn_reduce<<<dim3(ROWS, NKV), HD>>>(out);

    const int HEAD_OUT = NH * BQ * HD;        // 65536
    const int KV_OUT   = NKV * BQ * HD;       // 16384
    if (out_size >= HEAD_OUT + 2 * KV_OUT) {
        prep_kv<<<64, 256>>>(keys, vals, scale,
                             out + HEAD_OUT, out + HEAD_OUT + KV_OUT);
    }
}